// round 11
// baseline (speedup 1.0000x reference)
#include <cuda_runtime.h>
#include <cstdint>

#define HID   64
#define CHUNK 128
#define SEQS  4      // sequences per CTA
#define NTHR  256    // thread = (e, kq): 64 elements x 4 k-quarters
#define NBLK  256    // 256 * 4 = 1024 sequences

typedef unsigned long long ull;

__device__ __forceinline__ ull pk2(float a, float b) {
    ull r; asm("mov.b64 %0, {%1, %2};" : "=l"(r) : "f"(a), "f"(b)); return r;
}
__device__ __forceinline__ void upk2(ull v, float &a, float &b) {
    asm("mov.b64 {%0, %1}, %2;" : "=f"(a), "=f"(b) : "l"(v));
}
__device__ __forceinline__ ull ffma2(ull a, ull b, ull c) {
    ull d; asm("fma.rn.f32x2 %0, %1, %2, %3;" : "=l"(d) : "l"(a), "l"(b), "l"(c)); return d;
}
// single-MUFU tanh (sm_75+): MUFU.TANH
__device__ __forceinline__ float ftanh_(float x){
    float y; asm("tanh.approx.f32 %0, %1;" : "=f"(y) : "f"(x)); return y;
}
// sigmoid(x) = 0.5*tanh(0.5x) + 0.5
__device__ __forceinline__ float fsig(float x){
    return fmaf(0.5f, ftanh_(0.5f * x), 0.5f);
}

__global__ void pc_zero_kernel(float* o) { if (threadIdx.x == 0) o[0] = 0.0f; }

__global__ void __launch_bounds__(NTHR, 2)
pc_lstm_kernel(const int*   __restrict__ inds,
               const float* __restrict__ p,
               const float* __restrict__ ls_probs,
               const float* __restrict__ open_probs,
               const int*   __restrict__ open_slices,
               const float* __restrict__ open_hx,
               const float* __restrict__ W_ih,
               const float* __restrict__ W_hh,
               const float* __restrict__ b_ih,
               const float* __restrict__ b_hh,
               const float* __restrict__ W_out,
               const float* __restrict__ b_out,
               const int*   __restrict__ n_chunks_ptr,
               float*       __restrict__ out)
{
    __shared__ __align__(16) float  hspF[2][SEQS][HID];   // double-buffered h
    __shared__ __align__(16) float2 xsh2[SEQS][CHUNK];    // plain (x0,x1)
    __shared__ float  paysh[SEQS][CHUNK];
    __shared__ float  opwSh[SEQS];
    __shared__ float2 olpSh[SEQS];
    __shared__ int    baseSh[SEQS];

    const int tid  = threadIdx.x;
    const int e    = tid >> 2;        // element 0..63
    const int kq   = tid & 3;         // k-quarter
    const int kb   = kq * 16;         // k base
    const int w    = tid >> 5;        // warp 0..7; warps 0..3 <-> seqs in phase 4
    const int lane = tid & 31;

    const int rI = e, rF = 64 + e, rG = 128 + e, rO = 192 + e;

    // ---- W_hh: 4 rows x 16 k-values (k-quarter), k-pair packed: 32 ull = 64 regs ----
    ull wI[8], wF[8], wG[8], wO[8];
    #pragma unroll
    for (int k2 = 0; k2 < 8; ++k2) {
        int k = kb + 2 * k2;
        wI[k2] = pk2(W_hh[rI * HID + k], W_hh[rI * HID + k + 1]);
        wF[k2] = pk2(W_hh[rF * HID + k], W_hh[rF * HID + k + 1]);
        wG[k2] = pk2(W_hh[rG * HID + k], W_hh[rG * HID + k + 1]);
        wO[k2] = pk2(W_hh[rO * HID + k], W_hh[rO * HID + k + 1]);
    }

    // ---- own-gate (gate == kq) input constants and activation constants ----
    const int   rowOwn  = kq * 64 + e;
    const float biasOwn = b_ih[rowOwn] + b_hh[rowOwn];
    const float wiOwn0  = W_ih[rowOwn * 2 + 0];
    const float wiOwn1  = W_ih[rowOwn * 2 + 1];
    const bool  isG     = (kq == 2);
    const float preM    = isG ? 1.0f : 0.5f;   // y = postM*tanh(preM*x) + postA
    const float postM   = isG ? 1.0f : 0.5f;
    const float postA   = isG ? 0.0f : 0.5f;

    const float wo0 = W_out[2 * lane];
    const float wo1 = W_out[2 * lane + 1];
    const float bo  = b_out[0];

    if (tid < SEQS) {
        int q = blockIdx.x * SEQS + tid;
        baseSh[tid] = inds[q >> 4] + (q & 15);   // B2 == 16
        int sl = open_slices[q];
        olpSh[tid] = make_float2(__logf(p[2 * sl]), __logf(p[2 * sl + 1]));
        opwSh[tid] = open_probs[q] * (2.0f * ls_probs[q] - 1.0f);
    }

    // init c (redundant across kq lanes) and h (kq==0 publishes)
    float cc[SEQS];
    #pragma unroll
    for (int s = 0; s < SEQS; ++s) {
        int q = blockIdx.x * SEQS + s;
        cc[s] = open_hx[(q * 2 + 1) * HID + e];
        if (kq == 0) hspF[0][s][e] = open_hx[(q * 2 + 0) * HID + e];
    }
    __syncthreads();

    const int nch = n_chunks_ptr ? n_chunks_ptr[0] : 128;

    float  nd = 1.0f;            // survival chain (warps 0..3, redundant per lane)
    double lossAcc = 0.0;
    int    cur = 0;              // even #steps/chunk -> cur==0 at chunk starts

    for (int ch = 0; ch < nch; ++ch) {
        __syncthreads();  // previous chunk's xsh2/paysh fully consumed
        // ---- chunk preamble ----
        for (int i = tid; i < SEQS * CHUNK; i += NTHR) {
            int s  = i >> 7;
            int tt = i & (CHUNK - 1);
            int b  = baseSh[s] + ch * CHUNK;
            float2 pv = ((const float2*)p)[b + tt];
            float2 pz = ((const float2*)p)[b];
            xsh2[s][tt] = make_float2(pv.x - pz.x, pv.y - pz.y);
            paysh[s][tt] = opwSh[s] * ((__logf(pv.x) - olpSh[s].x) + (__logf(pv.y) - olpSh[s].y));
        }
        __syncthreads();

        #pragma unroll 1
        for (int t = 0; t < CHUNK; ++t) {
            // ---- matvec: 4 rows x k-quarter; 1 LDS.128 -> 8 FFMA2; bank-spread ----
            ull aI[SEQS], aF[SEQS], aG[SEQS], aO[SEQS];
            #pragma unroll
            for (int s = 0; s < SEQS; ++s) { aI[s]=0; aF[s]=0; aG[s]=0; aO[s]=0; }
            #pragma unroll
            for (int i = 0; i < 4; ++i) {
                int i2 = (i + kq) & 3;           // disjoint bank quads across kq
                #pragma unroll
                for (int s = 0; s < SEQS; ++s) {
                    ulonglong2 hh = *(const ulonglong2*)&hspF[cur][s][kb + 4 * i2];
                    aI[s] = ffma2(wI[2*i2],   hh.x, aI[s]);
                    aF[s] = ffma2(wF[2*i2],   hh.x, aF[s]);
                    aG[s] = ffma2(wG[2*i2],   hh.x, aG[s]);
                    aO[s] = ffma2(wO[2*i2],   hh.x, aO[s]);
                    aI[s] = ffma2(wI[2*i2+1], hh.y, aI[s]);
                    aF[s] = ffma2(wF[2*i2+1], hh.y, aF[s]);
                    aG[s] = ffma2(wG[2*i2+1], hh.y, aG[s]);
                    aO[s] = ffma2(wO[2*i2+1], hh.y, aO[s]);
                }
            }

            // ---- lagged phase 4 (step t-1): warps 0..3, overlaps FMA stream ----
            if (t && w < SEQS) {
                float2 hv = ((const float2*)hspF[cur][w])[lane];
                float part = fmaf(hv.x, wo0, hv.y * wo1);
                #pragma unroll
                for (int o = 16; o; o >>= 1)
                    part += __shfl_xor_sync(0xffffffffu, part, o);
                float raw = fsig(part + bo);
                float pay = paysh[w][t - 1];
                float adj = (t - 1 == 0) ? raw : raw * nd;
                lossAcc += (double)(adj * pay);
                nd *= (1.0f - raw);          // t-1 <= 126: always update
            }

            // ---- per-seq tail: fold, reduce-scatter, 1-MUFU gate, allgather ----
            const bool oddq = kq & 1;
            const bool hiq  = kq & 2;
            const int  base = lane & ~3;
            #pragma unroll
            for (int s = 0; s < SEQS; ++s) {
                float lo, hi;
                upk2(aI[s], lo, hi); float f0 = lo + hi;    // gate0 partial
                upk2(aF[s], lo, hi); float f1 = lo + hi;    // gate1
                upk2(aG[s], lo, hi); float f2 = lo + hi;    // gate2
                upk2(aO[s], lo, hi); float f3 = lo + hi;    // gate3

                // reduce-scatter: lane kq ends with gate kq's full sum (3 shfl)
                float sendA = oddq ? f0 : f1;
                float sendB = oddq ? f2 : f3;
                float recvA = __shfl_xor_sync(0xffffffffu, sendA, 1);
                float recvB = __shfl_xor_sync(0xffffffffu, sendB, 1);
                float nA = (oddq ? f1 : f0) + recvA;        // gate bit0==kq&1, bit1=0
                float nB = (oddq ? f3 : f2) + recvB;        // gate bit0==kq&1, bit1=1
                float sendC = hiq ? nA : nB;
                float recvC = __shfl_xor_sync(0xffffffffu, sendC, 2);
                float mine  = (hiq ? nB : nA) + recvC;      // full pre-act of gate kq

                // own-gate input term + single-MUFU activation
                float2 xv = xsh2[s][t];
                float pre = mine + fmaf(wiOwn1, xv.y, fmaf(wiOwn0, xv.x, biasOwn));
                float y = fmaf(postM, ftanh_(preM * pre), postA);

                // allgather by lane index (4 shfl): (si, sf, tg, so)
                float si = __shfl_sync(0xffffffffu, y, base);
                float sf = __shfl_sync(0xffffffffu, y, base + 1);
                float tg = __shfl_sync(0xffffffffu, y, base + 2);
                float so = __shfl_sync(0xffffffffu, y, base + 3);

                cc[s] = sf * cc[s] + si * tg;
                if (kq == 0) hspF[cur ^ 1][s][e] = so * ftanh_(cc[s]);
            }
            __syncthreads();   // single barrier: h published, buffers rotate
            cur ^= 1;
        }

        // ---- trailing phase 4 for t = CHUNK-1 ----
        if (w < SEQS) {
            float2 hv = ((const float2*)hspF[cur][w])[lane];
            float part = fmaf(hv.x, wo0, hv.y * wo1);
            #pragma unroll
            for (int o = 16; o; o >>= 1)
                part += __shfl_xor_sync(0xffffffffu, part, o);
            float raw = fsig(part + bo);
            float pay = paysh[w][CHUNK - 1];
            lossAcc += (double)(raw * nd * pay);
            // last element of chunk: nd NOT updated (cumprod over [:-1])
        }
    }

    if (w < SEQS && lane == 0) atomicAdd(out, (float)lossAcc);
}

extern "C" void kernel_launch(void* const* d_in, const int* in_sizes, int n_in,
                              void* d_out, int out_size)
{
    const int*   inds        = (const int*)  d_in[0];
    const float* p           = (const float*)d_in[1];
    const float* ls_probs    = (const float*)d_in[2];
    const float* open_probs  = (const float*)d_in[3];
    const int*   open_slices = (const int*)  d_in[4];
    const float* open_hx     = (const float*)d_in[5];
    const float* W_ih        = (const float*)d_in[6];
    const float* W_hh        = (const float*)d_in[7];
    const float* b_ih        = (const float*)d_in[8];
    const float* b_hh        = (const float*)d_in[9];
    const float* W_out       = (const float*)d_in[10];
    const float* b_out       = (const float*)d_in[11];
    const int*   n_chunks    = (n_in > 12) ? (const int*)d_in[12] : nullptr;

    float* out = (float*)d_out;

    pc_zero_kernel<<<1, 32>>>(out);
    pc_lstm_kernel<<<NBLK, NTHR>>>(inds, p, ls_probs, open_probs, open_slices,
                                   open_hx, W_ih, W_hh, b_ih, b_hh,
                                   W_out, b_out, n_chunks, out);
}